// round 6
// baseline (speedup 1.0000x reference)
#include <cuda_runtime.h>

// Problem constants
#define B_    4096
#define NTOK  49
#define DIMC  192
#define NH    6
#define HD    32
#define NWIN  64

typedef unsigned long long u64;

// Scratch (device globals — allocation-free per harness rules)
__device__ float g_q[(size_t)B_ * NH * NTOK * HD];   // 38,535,168 f32, q pre-scaled
__device__ float g_k[(size_t)B_ * NH * NTOK * HD];
__device__ float g_v[(size_t)B_ * NH * NTOK * HD];
__device__ float g_ctx[(size_t)B_ * NTOK * DIMC];    // attention output pre-proj

__device__ __forceinline__ void ffma2(u64& acc, u64 a, u64 b) {
    asm("fma.rn.f32x2 %0, %1, %2, %0;" : "+l"(acc) : "l"(a), "l"(b));
}

// ---------------------------------------------------------------------------
// Kernel 1: QKV GEMM  y[m,j] = sum_k x[m,k] * W[j,k] + b[j]
// M = B_*NTOK = 200704, N = 576, K = 192.
// CTA tile 128(M) x 64(N), 256 threads, per-thread 8x4 via f32x2 pairs.
// Scatter epilogue into g_q/g_k/g_v with layout [B, H, N, hd]; q *= scale.
// ---------------------------------------------------------------------------
__global__ __launch_bounds__(256, 2)
void qkv_gemm_kernel(const float* __restrict__ X,
                     const float* __restrict__ W,
                     const float* __restrict__ bias)
{
    __shared__ float As[16][128];    // [k][m]
    __shared__ float Bsd[16][128];   // [k][2*j] duplicated pairs for f32x2

    const int tid = threadIdx.x;
    const int m0  = blockIdx.y * 128;
    const int j0  = blockIdx.x * 64;
    const int ty  = tid >> 4;        // 0..15 (M dir, 8 rows each)
    const int tx  = tid & 15;        // 0..15 (N dir, 4 cols each)

    u64 acc2[4][4];
#pragma unroll
    for (int i = 0; i < 4; i++)
#pragma unroll
        for (int j = 0; j < 4; j++) acc2[i][j] = 0ull;

    for (int k0 = 0; k0 < DIMC; k0 += 16) {
        // Load A tile: 128 rows x 16 k = 512 float4, 2 per thread
#pragma unroll
        for (int t = 0; t < 2; t++) {
            const int f   = tid * 2 + t;
            const int row = f >> 2;
            const int cg  = f & 3;
            const float4 v4 = *reinterpret_cast<const float4*>(
                X + (size_t)(m0 + row) * DIMC + k0 + cg * 4);
            As[cg * 4 + 0][row] = v4.x;
            As[cg * 4 + 1][row] = v4.y;
            As[cg * 4 + 2][row] = v4.z;
            As[cg * 4 + 3][row] = v4.w;
        }
        // Load B tile: 64 j-rows x 16 k = 256 float4, 1 per thread, duplicated
        {
            const int row = tid >> 2;
            const int cg  = tid & 3;
            const float4 v4 = *reinterpret_cast<const float4*>(
                W + (size_t)(j0 + row) * DIMC + k0 + cg * 4);
            Bsd[cg * 4 + 0][2 * row] = v4.x; Bsd[cg * 4 + 0][2 * row + 1] = v4.x;
            Bsd[cg * 4 + 1][2 * row] = v4.y; Bsd[cg * 4 + 1][2 * row + 1] = v4.y;
            Bsd[cg * 4 + 2][2 * row] = v4.z; Bsd[cg * 4 + 2][2 * row + 1] = v4.z;
            Bsd[cg * 4 + 3][2 * row] = v4.w; Bsd[cg * 4 + 3][2 * row + 1] = v4.w;
        }
        __syncthreads();
#pragma unroll
        for (int kk = 0; kk < 16; kk++) {
            u64 a2[4], b2[4];
            const u64* ap = reinterpret_cast<const u64*>(&As[kk][ty * 8]);
            const u64* bp = reinterpret_cast<const u64*>(&Bsd[kk][tx * 8]);
#pragma unroll
            for (int i = 0; i < 4; i++) { a2[i] = ap[i]; b2[i] = bp[i]; }
#pragma unroll
            for (int i = 0; i < 4; i++)
#pragma unroll
                for (int j = 0; j < 4; j++)
                    ffma2(acc2[i][j], a2[i], b2[j]);
        }
        __syncthreads();
    }

    const float scale = 0.17677669529663687f;  // hd^-0.5
#pragma unroll
    for (int i = 0; i < 4; i++) {
#pragma unroll
        for (int j = 0; j < 4; j++) {
            float2 p = *reinterpret_cast<float2*>(&acc2[i][j]);
            const int jj = j0 + tx * 4 + j;
            const float bv = bias[jj];
            const int t = jj / DIMC;
            const int r = jj - t * DIMC;
            const int h = r >> 5;
            const int d = r & 31;
#pragma unroll
            for (int e = 0; e < 2; e++) {
                const int m  = m0 + ty * 8 + 2 * i + e;
                const int bi = m / NTOK;
                const int ni = m - bi * NTOK;
                const int dst = ((bi * NH + h) * NTOK + ni) * HD + d;
                const float val = (e ? p.y : p.x) + bv;
                if (t == 0)      g_q[dst] = val * scale;
                else if (t == 1) g_k[dst] = val;
                else             g_v[dst] = val;
            }
        }
    }
}

// ---------------------------------------------------------------------------
// Kernel 2: per-(window, head) attention.
// S = q kᵀ + rpb[rel_idx] + mask ; softmax ; attn out ; ctx = P v.
// ---------------------------------------------------------------------------
__global__ __launch_bounds__(256)
void attn_kernel(const float* __restrict__ mask,
                 const float* __restrict__ rpb,
                 const int*   __restrict__ rel_idx,
                 float* __restrict__ attn_out)
{
    __shared__ float qs[NTOK * 33];
    __shared__ float ks[NTOK * 33];
    __shared__ float vs[NTOK * 33];
    __shared__ float S[NTOK * 50];

    const int bh  = blockIdx.x;
    const int b   = bh / NH;
    const int h   = bh - b * NH;
    const int tid = threadIdx.x;

    const size_t base = (size_t)bh * (NTOK * HD);
    for (int idx = tid; idx < NTOK * HD; idx += 256) {
        const int r = idx >> 5, d = idx & 31;
        qs[r * 33 + d] = g_q[base + idx];
        ks[r * 33 + d] = g_k[base + idx];
        vs[r * 33 + d] = g_v[base + idx];
    }
    __syncthreads();

    const float* mrow = mask + (size_t)(b & (NWIN - 1)) * (NTOK * NTOK);
    for (int idx = tid; idx < NTOK * NTOK; idx += 256) {
        const int i = idx / NTOK;
        const int j = idx - i * NTOK;
        const float* qp = &qs[i * 33];
        const float* kp = &ks[j * 33];
        float s = 0.f;
#pragma unroll
        for (int d = 0; d < HD; d++) s += qp[d] * kp[d];
        s += rpb[rel_idx[idx] * NH + h] + mrow[idx];
        S[i * 50 + j] = s;
    }
    __syncthreads();

    const int lane = tid & 31;
    const int wid  = tid >> 5;
    for (int i = wid; i < NTOK; i += 8) {
        float mval = -3.4e38f;
        for (int j = lane; j < NTOK; j += 32) mval = fmaxf(mval, S[i * 50 + j]);
#pragma unroll
        for (int o = 16; o > 0; o >>= 1)
            mval = fmaxf(mval, __shfl_xor_sync(0xffffffffu, mval, o));
        float sum = 0.f;
        for (int j = lane; j < NTOK; j += 32) {
            const float e = expf(S[i * 50 + j] - mval);
            S[i * 50 + j] = e;
            sum += e;
        }
#pragma unroll
        for (int o = 16; o > 0; o >>= 1)
            sum += __shfl_xor_sync(0xffffffffu, sum, o);
        const float inv = 1.0f / sum;
        for (int j = lane; j < NTOK; j += 32) {
            const float pv = S[i * 50 + j] * inv;
            S[i * 50 + j] = pv;
            if (attn_out)
                attn_out[(size_t)bh * (NTOK * NTOK) + i * NTOK + j] = pv;
        }
    }
    __syncthreads();

    for (int idx = tid; idx < NTOK * HD; idx += 256) {
        const int i = idx >> 5, d = idx & 31;
        const float* pp = &S[i * 50];
        float acc = 0.f;
#pragma unroll
        for (int j = 0; j < NTOK; j++) acc += pp[j] * vs[j * 33 + d];
        g_ctx[((size_t)b * NTOK + i) * DIMC + h * HD + d] = acc;
    }
}

// ---------------------------------------------------------------------------
// Kernel 3: output projection  out = ctx @ proj_w.T + proj_b
// M = 200704, N = 192, K = 192. Same f32x2 GEMM core.
// ---------------------------------------------------------------------------
__global__ __launch_bounds__(256, 2)
void proj_gemm_kernel(const float* __restrict__ W,
                      const float* __restrict__ bias,
                      float* __restrict__ out)
{
    __shared__ float As[16][128];
    __shared__ float Bsd[16][128];

    const int tid = threadIdx.x;
    const int m0  = blockIdx.y * 128;
    const int j0  = blockIdx.x * 64;
    const int ty  = tid >> 4;
    const int tx  = tid & 15;

    u64 acc2[4][4];
#pragma unroll
    for (int i = 0; i < 4; i++)
#pragma unroll
        for (int j = 0; j < 4; j++) acc2[i][j] = 0ull;

    for (int k0 = 0; k0 < DIMC; k0 += 16) {
#pragma unroll
        for (int t = 0; t < 2; t++) {
            const int f   = tid * 2 + t;
            const int row = f >> 2;
            const int cg  = f & 3;
            const float4 v4 = *reinterpret_cast<const float4*>(
                g_ctx + (size_t)(m0 + row) * DIMC + k0 + cg * 4);
            As[cg * 4 + 0][row] = v4.x;
            As[cg * 4 + 1][row] = v4.y;
            As[cg * 4 + 2][row] = v4.z;
            As[cg * 4 + 3][row] = v4.w;
        }
        {
            const int row = tid >> 2;
            const int cg  = tid & 3;
            const float4 v4 = *reinterpret_cast<const float4*>(
                W + (size_t)(j0 + row) * DIMC + k0 + cg * 4);
            Bsd[cg * 4 + 0][2 * row] = v4.x; Bsd[cg * 4 + 0][2 * row + 1] = v4.x;
            Bsd[cg * 4 + 1][2 * row] = v4.y; Bsd[cg * 4 + 1][2 * row + 1] = v4.y;
            Bsd[cg * 4 + 2][2 * row] = v4.z; Bsd[cg * 4 + 2][2 * row + 1] = v4.z;
            Bsd[cg * 4 + 3][2 * row] = v4.w; Bsd[cg * 4 + 3][2 * row + 1] = v4.w;
        }
        __syncthreads();
#pragma unroll
        for (int kk = 0; kk < 16; kk++) {
            u64 a2[4], b2[4];
            const u64* ap = reinterpret_cast<const u64*>(&As[kk][ty * 8]);
            const u64* bp = reinterpret_cast<const u64*>(&Bsd[kk][tx * 8]);
#pragma unroll
            for (int i = 0; i < 4; i++) { a2[i] = ap[i]; b2[i] = bp[i]; }
#pragma unroll
            for (int i = 0; i < 4; i++)
#pragma unroll
                for (int j = 0; j < 4; j++)
                    ffma2(acc2[i][j], a2[i], b2[j]);
        }
        __syncthreads();
    }

#pragma unroll
    for (int i = 0; i < 4; i++) {
#pragma unroll
        for (int j = 0; j < 4; j++) {
            float2 p = *reinterpret_cast<float2*>(&acc2[i][j]);
            const int jj = j0 + tx * 4 + j;
            const float bv = bias[jj];
#pragma unroll
            for (int e = 0; e < 2; e++) {
                const int m = m0 + ty * 8 + 2 * i + e;
                out[(size_t)m * DIMC + jj] = (e ? p.y : p.x) + bv;
            }
        }
    }
}

// ---------------------------------------------------------------------------
// Launch. Inputs (metadata order): x, mask, qkv_w, qkv_b, proj_w, proj_b,
// rpb_table, rel_idx. Output: out [B_,N,C] (and attn [B_,H,N,N] appended
// if out_size covers both, tuple order).
// ---------------------------------------------------------------------------
extern "C" void kernel_launch(void* const* d_in, const int* in_sizes, int n_in,
                              void* d_out, int out_size)
{
    const float* x      = (const float*)d_in[0];
    const float* mask   = (const float*)d_in[1];
    const float* qkv_w  = (const float*)d_in[2];
    const float* qkv_b  = (const float*)d_in[3];
    const float* proj_w = (const float*)d_in[4];
    const float* proj_b = (const float*)d_in[5];
    const float* rpb    = (const float*)d_in[6];
    const int*   relidx = (const int*)d_in[7];

    float* out = (float*)d_out;
    const long OUT_ELEMS  = (long)B_ * NTOK * DIMC;          // 38,535,168
    const long ATTN_ELEMS = (long)B_ * NH * NTOK * NTOK;     // 59,006,976
    float* attn_out = nullptr;
    if ((long)out_size >= OUT_ELEMS + ATTN_ELEMS) attn_out = out + OUT_ELEMS;

    const dim3 blk(256);
    qkv_gemm_kernel<<<dim3(576 / 64, (B_ * NTOK) / 128), blk>>>(x, qkv_w, qkv_b);
    attn_kernel<<<B_ * NH, blk>>>(mask, rpb, relidx, attn_out);
    proj_gemm_kernel<<<dim3(DIMC / 64, (B_ * NTOK) / 128), blk>>>(proj_w, proj_b, out);

    (void)in_sizes; (void)n_in;
}